// round 13
// baseline (speedup 1.0000x reference)
#include <cuda_runtime.h>
#include <cuda_bf16.h>
#include <cstdint>

// MultiVariatePoly via mma.sync (HMMA) bf16 split-2 GEMM — sm_100-safe (no tcgen05).
// Per 128-point CTA: D[pt, feat(i,j)] = A[128,32] @ B[104,32]^T
//   A row (point):   [Zhi(10) | Zlo(10) | Zhi(10) | 0 0]   (Z = Legendre(z), bf16 split)
//   B row (feature): [Whi(10) | Whi(10) | Wlo(10) | 0 0]
//   => D = sum_k Whi*Zhi + Whi*Zlo + Wlo*Zhi   (drops wlo*zlo ~ 2^-16 rel)
// 4 warps x 32 points; 13 n8-tiles in two phases (7+6) staged to smem (stride 56);
// epilogue: each thread reads its own point's D row and folds Px[i]*Py[j] with
// compile-time indices. out = acc + b.
// (Resubmission of R12 — previous round failed on container infra, no data.)

#define NP1 10
#define TPB 128
#define ASTR 40    // bf16 per A/B row: 80B (16B-multiple, ldmatrix-friendly)
#define BROWS 104  // 100 features padded to 13 n8-tiles
#define DSTR 56    // fp32 per D-staging row (7 tiles * 8)

typedef uint32_t u32;

__device__ __forceinline__ u32 smem_u32(const void* p) {
    u32 a;
    asm("{ .reg .u64 t; cvta.to.shared.u64 t, %1; cvt.u32.u64 %0, t; }" : "=r"(a) : "l"(p));
    return a;
}
__device__ __forceinline__ void ldmatrix_x4(u32* r, u32 addr) {
    asm volatile("ldmatrix.sync.aligned.m8n8.x4.shared.b16 {%0,%1,%2,%3}, [%4];"
                 : "=r"(r[0]), "=r"(r[1]), "=r"(r[2]), "=r"(r[3]) : "r"(addr));
}
__device__ __forceinline__ void ldmatrix_x2(u32* r, u32 addr) {
    asm volatile("ldmatrix.sync.aligned.m8n8.x2.shared.b16 {%0,%1}, [%2];"
                 : "=r"(r[0]), "=r"(r[1]) : "r"(addr));
}
__device__ __forceinline__ void mma_bf16(float& d0, float& d1, float& d2, float& d3,
                                         const u32* a, const u32* b) {
    asm volatile(
        "mma.sync.aligned.m16n8k16.row.col.f32.bf16.bf16.f32 "
        "{%0,%1,%2,%3}, {%4,%5,%6,%7}, {%8,%9}, {%0,%1,%2,%3};"
        : "+f"(d0), "+f"(d1), "+f"(d2), "+f"(d3)
        : "r"(a[0]), "r"(a[1]), "r"(a[2]), "r"(a[3]), "r"(b[0]), "r"(b[1]));
}

__device__ __forceinline__ void legendre1(float x, float P[NP1]) {
    P[0] = 1.0f;
    P[1] = x;
#pragma unroll
    for (int k = 1; k < NP1 - 1; k++) {
        const float c1 = (float)(2 * k + 1) / (float)(k + 1);
        const float c2 = -(float)k / (float)(k + 1);
        P[k + 1] = c1 * x * P[k] + c2 * P[k - 1];
    }
}

__global__ void __launch_bounds__(TPB, 4)
poly_mma_kernel(const float* __restrict__ x, const float* __restrict__ W,
                const float* __restrict__ bptr, float* __restrict__ out, int N) {
    __shared__ __align__(16) __nv_bfloat16 sA[128 * ASTR];    // 10 KB
    __shared__ __align__(16) __nv_bfloat16 sB[BROWS * ASTR];  //  8.1 KB
    __shared__ __align__(16) float sD[128 * DSTR];            // 28 KB

    const int tid = threadIdx.x;
    const int lane = tid & 31;
    const int wrp = tid >> 5;
    const u32 smA = smem_u32(sA);
    const u32 smB = smem_u32(sB);

    // ---- per-point setup ----
    int p = blockIdx.x * TPB + tid;
    int pc = (p < N) ? p : (N - 1);
    float x0 = x[3 * pc + 0], x1 = x[3 * pc + 1], x2 = x[3 * pc + 2];
    float bb = *bptr;

    float Px[NP1], Py[NP1], Pz[NP1];
    legendre1(x0, Px);
    legendre1(x1, Py);
    legendre1(x2, Pz);

    // ---- A row (this thread's point): [zhi | zlo | zhi | 0 0] ----
    {
        __nv_bfloat16 zh[NP1], zl[NP1];
#pragma unroll
        for (int k = 0; k < NP1; k++) {
            zh[k] = __float2bfloat16(Pz[k]);
            zl[k] = __float2bfloat16(Pz[k] - __bfloat162float(zh[k]));
        }
        __nv_bfloat162* row = reinterpret_cast<__nv_bfloat162*>(sA + tid * ASTR);
#pragma unroll
        for (int cc = 0; cc < 5; cc++) {
            __nv_bfloat162 v; v.x = zh[2 * cc]; v.y = zh[2 * cc + 1];
            row[cc] = v;
        }
#pragma unroll
        for (int cc = 0; cc < 5; cc++) {
            __nv_bfloat162 v; v.x = zl[2 * cc]; v.y = zl[2 * cc + 1];
            row[5 + cc] = v;
        }
#pragma unroll
        for (int cc = 0; cc < 5; cc++) {
            __nv_bfloat162 v; v.x = zh[2 * cc]; v.y = zh[2 * cc + 1];
            row[10 + cc] = v;
        }
        __nv_bfloat162 z2; z2.x = __float2bfloat16(0.f); z2.y = z2.x;
        row[15] = z2;  // cols 30,31 (read by ldmatrix) must be zero
    }

    // ---- B row (feature tid): [whi | whi | wlo | 0 0]; rows 100..103 all-zero ----
    if (tid < BROWS) {
        __nv_bfloat162* row = reinterpret_cast<__nv_bfloat162*>(sB + tid * ASTR);
        if (tid < 100) {
            const float* wr = W + 10 * tid;
            __nv_bfloat16 wh[NP1], wl[NP1];
#pragma unroll
            for (int k = 0; k < NP1; k++) {
                float w = wr[k];
                wh[k] = __float2bfloat16(w);
                wl[k] = __float2bfloat16(w - __bfloat162float(wh[k]));
            }
#pragma unroll
            for (int cc = 0; cc < 5; cc++) {
                __nv_bfloat162 v; v.x = wh[2 * cc]; v.y = wh[2 * cc + 1];
                row[cc] = v;
                row[5 + cc] = v;
            }
#pragma unroll
            for (int cc = 0; cc < 5; cc++) {
                __nv_bfloat162 v; v.x = wl[2 * cc]; v.y = wl[2 * cc + 1];
                row[10 + cc] = v;
            }
            __nv_bfloat162 z2; z2.x = __float2bfloat16(0.f); z2.y = z2.x;
            row[15] = z2;
        } else {
            __nv_bfloat162 z2; z2.x = __float2bfloat16(0.f); z2.y = z2.x;
#pragma unroll
            for (int cc = 0; cc < 16; cc++) row[cc] = z2;
        }
    }
    __syncthreads();

    // ---- A fragments (once per warp): 2 m16-tiles x 2 k16-steps ----
    // ldmatrix.x4 lane->address: matrix m = lane/8, row-in-tile = lane%8
    //   m0: rows 0-7  k-lo | m1: rows 8-15 k-lo | m2: rows 0-7 k-hi | m3: rows 8-15 k-hi
    u32 afr[2][2][4];
    {
        int m = lane >> 3, ri = lane & 7;
        int arow_base = wrp * 32 + ri + ((m & 1) << 3);
        int acol_off = (m & 2) ? 8 : 0;
#pragma unroll
        for (int mt = 0; mt < 2; mt++)
#pragma unroll
            for (int ks = 0; ks < 2; ks++) {
                u32 ad = smA + ((arow_base + 16 * mt) * ASTR + ks * 16 + acol_off) * 2;
                ldmatrix_x4(afr[mt][ks], ad);
            }
    }

    // B ldmatrix lane->address (x2, lanes 0-15): matrix = l15/8 (k-lo / k-hi), row = n
    int l15 = lane & 15;
    int mb = l15 >> 3, rib = l15 & 7;

    float acc = 0.f;

#pragma unroll
    for (int ph = 0; ph < 2; ph++) {
        const int ntb = ph ? 7 : 0;
        const int nte = ph ? 13 : 7;
#pragma unroll
        for (int nt = ntb; nt < nte; nt++) {
            int n0 = nt * 8;
            u32 bf0[2], bf1[2];
            u32 bad = smB + ((n0 + rib) * ASTR + (mb ? 8 : 0)) * 2;
            ldmatrix_x2(bf0, bad);        // k16-step 0 (cols 0..15)
            ldmatrix_x2(bf1, bad + 32);   // k16-step 1 (cols 16..31)
#pragma unroll
            for (int mt = 0; mt < 2; mt++) {
                float d0 = 0.f, d1 = 0.f, d2 = 0.f, d3 = 0.f;
                mma_bf16(d0, d1, d2, d3, afr[mt][0], bf0);
                mma_bf16(d0, d1, d2, d3, afr[mt][1], bf1);
                // D fragment: c0,c1 -> (row lane/4,   col 2(lane%4))
                //             c2,c3 -> (row lane/4+8, col 2(lane%4))
                int rg = wrp * 32 + 16 * mt + (lane >> 2);
                int cg = (nt - ntb) * 8 + 2 * (lane & 3);
                u32 a0 = smem_u32(sD) + (rg * DSTR + cg) * 4;
                u32 a1 = smem_u32(sD) + ((rg + 8) * DSTR + cg) * 4;
                asm volatile("st.shared.v2.f32 [%0], {%1,%2};" :: "r"(a0), "f"(d0), "f"(d1) : "memory");
                asm volatile("st.shared.v2.f32 [%0], {%1,%2};" :: "r"(a1), "f"(d2), "f"(d3) : "memory");
            }
        }
        __syncthreads();

        // ---- epilogue for this phase: own point's row, compile-time (i,j) ----
        const float4* drow = reinterpret_cast<const float4*>(sD + tid * DSTR);
        if (ph == 0) {
#pragma unroll
            for (int q = 0; q < 14; q++) {  // f = 0..55
                float4 v = drow[q];
                acc += v.x * (Px[(q * 4 + 0) / 10] * Py[(q * 4 + 0) % 10]);
                acc += v.y * (Px[(q * 4 + 1) / 10] * Py[(q * 4 + 1) % 10]);
                acc += v.z * (Px[(q * 4 + 2) / 10] * Py[(q * 4 + 2) % 10]);
                acc += v.w * (Px[(q * 4 + 3) / 10] * Py[(q * 4 + 3) % 10]);
            }
            __syncthreads();  // protect sD before phase-1 overwrites
        } else {
#pragma unroll
            for (int q = 0; q < 11; q++) {  // f = 56..99 (44 floats)
                float4 v = drow[q];
                acc += v.x * (Px[(56 + q * 4 + 0) / 10] * Py[(56 + q * 4 + 0) % 10]);
                acc += v.y * (Px[(56 + q * 4 + 1) / 10] * Py[(56 + q * 4 + 1) % 10]);
                acc += v.z * (Px[(56 + q * 4 + 2) / 10] * Py[(56 + q * 4 + 2) % 10]);
                acc += v.w * (Px[(56 + q * 4 + 3) / 10] * Py[(56 + q * 4 + 3) % 10]);
            }
        }
    }

    if (p < N) out[p] = acc + bb;
}

extern "C" void kernel_launch(void* const* d_in, const int* in_sizes, int n_in,
                              void* d_out, int out_size) {
    int ib = -1, ix = -1, iw = -1;
    int max_sz = -1;
    for (int i = 0; i < n_in; i++) {
        if (in_sizes[i] == 1 && ib < 0) ib = i;
        else if (in_sizes[i] > max_sz) { max_sz = in_sizes[i]; ix = i; }
    }
    for (int i = 0; i < n_in; i++) {
        if (i != ib && i != ix) { iw = i; break; }
    }

    const float* x = (const float*)d_in[ix];
    const float* W = (const float*)d_in[iw];
    const float* b = (const float*)d_in[ib];
    float* out = (float*)d_out;

    int N = in_sizes[ix] / 3;
    int grid = (N + TPB - 1) / TPB;  // 128 points per CTA

    poly_mma_kernel<<<grid, TPB>>>(x, W, b, out, N);
}

// round 14
// speedup vs baseline: 1.1257x; 1.1257x over previous
#include <cuda_runtime.h>
#include <cuda_bf16.h>
#include <cstdint>

// MultiVariatePoly via mma.sync (HMMA) bf16 split-2 GEMM, fused epilogue.
// Per 128-point CTA: D[pt, f(i,j)] = A[128,32] @ B[104,32]^T
//   A row (point):   [Zhi(10) | Zlo(10) | Zhi(10) | 0 0]
//   B row (feature): [Whi(10) | Whi(10) | Wlo(10) | 0 0]
// Coefficients Px[i]*Py[j] are applied to D fragments IN the mma loop (Px/Py
// read from shared per fragment row); per-point partials reduced with 2
// shfl.bfly. No D staging, one barrier, 29 KB smem -> 6 CTAs/SM, single wave.

#define NP1 10
#define TPB 128
#define ASTR 40    // bf16 per A/B row (80 B)
#define BROWS 104  // 13 n8-tiles
#define PSTR 20    // floats per sP row: Px[10] | Py[10]

typedef uint32_t u32;

__device__ __forceinline__ u32 smem_u32(const void* p) {
    u32 a;
    asm("{ .reg .u64 t; cvta.to.shared.u64 t, %1; cvt.u32.u64 %0, t; }" : "=r"(a) : "l"(p));
    return a;
}
__device__ __forceinline__ void ldmatrix_x4(u32* r, u32 addr) {
    asm volatile("ldmatrix.sync.aligned.m8n8.x4.shared.b16 {%0,%1,%2,%3}, [%4];"
                 : "=r"(r[0]), "=r"(r[1]), "=r"(r[2]), "=r"(r[3]) : "r"(addr));
}
__device__ __forceinline__ void ldmatrix_x2(u32* r, u32 addr) {
    asm volatile("ldmatrix.sync.aligned.m8n8.x2.shared.b16 {%0,%1}, [%2];"
                 : "=r"(r[0]), "=r"(r[1]) : "r"(addr));
}
__device__ __forceinline__ void mma_bf16(float& d0, float& d1, float& d2, float& d3,
                                         const u32* a, const u32* b) {
    asm volatile(
        "mma.sync.aligned.m16n8k16.row.col.f32.bf16.bf16.f32 "
        "{%0,%1,%2,%3}, {%4,%5,%6,%7}, {%8,%9}, {%0,%1,%2,%3};"
        : "+f"(d0), "+f"(d1), "+f"(d2), "+f"(d3)
        : "r"(a[0]), "r"(a[1]), "r"(a[2]), "r"(a[3]), "r"(b[0]), "r"(b[1]));
}

__device__ __forceinline__ void legendre1(float x, float P[NP1]) {
    P[0] = 1.0f;
    P[1] = x;
#pragma unroll
    for (int k = 1; k < NP1 - 1; k++) {
        const float c1 = (float)(2 * k + 1) / (float)(k + 1);
        const float c2 = -(float)k / (float)(k + 1);
        P[k + 1] = c1 * x * P[k] + c2 * P[k - 1];
    }
}

__global__ void __launch_bounds__(TPB, 6)
poly_mma_kernel(const float* __restrict__ x, const float* __restrict__ W,
                const float* __restrict__ bptr, float* __restrict__ out, int N) {
    __shared__ __align__(16) __nv_bfloat16 sA[128 * ASTR];    // 10 KB
    __shared__ __align__(16) __nv_bfloat16 sB[BROWS * ASTR];  //  8.1 KB
    __shared__ __align__(8) float sP[128 * PSTR];             // 10 KB: Px|Py per point

    const int tid = threadIdx.x;
    const int lane = tid & 31;
    const int wrp = tid >> 5;
    const u32 smA = smem_u32(sA);
    const u32 smB = smem_u32(sB);

    // ---- per-point setup ----
    int p = blockIdx.x * TPB + tid;
    int pc = (p < N) ? p : (N - 1);
    float x0 = x[3 * pc + 0], x1 = x[3 * pc + 1], x2 = x[3 * pc + 2];
    float bb = *bptr;

    {
        float Px[NP1], Py[NP1], Pz[NP1];
        legendre1(x0, Px);
        legendre1(x1, Py);
        legendre1(x2, Pz);

        // Px/Py to shared (consumed per-fragment in the mma loop)
        float2* prow = reinterpret_cast<float2*>(sP + tid * PSTR);
#pragma unroll
        for (int k = 0; k < 5; k++) prow[k] = make_float2(Px[2 * k], Px[2 * k + 1]);
#pragma unroll
        for (int k = 0; k < 5; k++) prow[5 + k] = make_float2(Py[2 * k], Py[2 * k + 1]);

        // A row (this point): [zhi | zlo | zhi | 0 0]
        __nv_bfloat16 zh[NP1], zl[NP1];
#pragma unroll
        for (int k = 0; k < NP1; k++) {
            zh[k] = __float2bfloat16(Pz[k]);
            zl[k] = __float2bfloat16(Pz[k] - __bfloat162float(zh[k]));
        }
        __nv_bfloat162* row = reinterpret_cast<__nv_bfloat162*>(sA + tid * ASTR);
#pragma unroll
        for (int cc = 0; cc < 5; cc++) {
            __nv_bfloat162 v; v.x = zh[2 * cc]; v.y = zh[2 * cc + 1];
            row[cc] = v;
        }
#pragma unroll
        for (int cc = 0; cc < 5; cc++) {
            __nv_bfloat162 v; v.x = zl[2 * cc]; v.y = zl[2 * cc + 1];
            row[5 + cc] = v;
        }
#pragma unroll
        for (int cc = 0; cc < 5; cc++) {
            __nv_bfloat162 v; v.x = zh[2 * cc]; v.y = zh[2 * cc + 1];
            row[10 + cc] = v;
        }
        __nv_bfloat162 z2; z2.x = __float2bfloat16(0.f); z2.y = z2.x;
        row[15] = z2;  // cols 30,31 read by ldmatrix must be 0
    }

    // ---- B row (feature tid): [whi | whi | wlo | 0 0]; rows 100..103 zero ----
    if (tid < BROWS) {
        __nv_bfloat162* row = reinterpret_cast<__nv_bfloat162*>(sB + tid * ASTR);
        if (tid < 100) {
            const float* wr = W + 10 * tid;
            __nv_bfloat16 wh[NP1], wl[NP1];
#pragma unroll
            for (int k = 0; k < NP1; k++) {
                float w = wr[k];
                wh[k] = __float2bfloat16(w);
                wl[k] = __float2bfloat16(w - __bfloat162float(wh[k]));
            }
#pragma unroll
            for (int cc = 0; cc < 5; cc++) {
                __nv_bfloat162 v; v.x = wh[2 * cc]; v.y = wh[2 * cc + 1];
                row[cc] = v;
                row[5 + cc] = v;
            }
#pragma unroll
            for (int cc = 0; cc < 5; cc++) {
                __nv_bfloat162 v; v.x = wl[2 * cc]; v.y = wl[2 * cc + 1];
                row[10 + cc] = v;
            }
            __nv_bfloat162 z2; z2.x = __float2bfloat16(0.f); z2.y = z2.x;
            row[15] = z2;
        } else {
            __nv_bfloat162 z2; z2.x = __float2bfloat16(0.f); z2.y = z2.x;
#pragma unroll
            for (int cc = 0; cc < 16; cc++) row[cc] = z2;
        }
    }
    __syncthreads();  // the only barrier

    // ---- A fragments (verified mapping from R13) ----
    u32 afr[2][2][4];
    {
        int m = lane >> 3, ri = lane & 7;
        int arow_base = wrp * 32 + ri + ((m & 1) << 3);
        int acol_off = (m & 2) ? 8 : 0;
#pragma unroll
        for (int mt = 0; mt < 2; mt++)
#pragma unroll
            for (int ks = 0; ks < 2; ks++) {
                u32 ad = smA + ((arow_base + 16 * mt) * ASTR + ks * 16 + acol_off) * 2;
                ldmatrix_x4(afr[mt][ks], ad);
            }
    }

    int l15 = lane & 15;
    int mb = l15 >> 3, rib = l15 & 7;

    // Fragment-row bases into sP for the 4 points this thread touches:
    //   mt0: rg, rg+8 ; mt1: rg+16, rg+24  with rg = wrp*32 + (lane>>2)
    const int rg = wrp * 32 + (lane >> 2);
    const float* pr00 = sP + (rg +  0) * PSTR;
    const float* pr01 = sP + (rg +  8) * PSTR;
    const float* pr10 = sP + (rg + 16) * PSTR;
    const float* pr11 = sP + (rg + 24) * PSTR;

    const int dlo = 2 * (lane & 3);  // feature offset within n8-tile (f0 even)

    float acc00 = 0.f, acc01 = 0.f, acc10 = 0.f, acc11 = 0.f;

#pragma unroll
    for (int nt = 0; nt < 13; nt++) {
        const int n0 = nt * 8;
        u32 bf0[2], bf1[2];
        u32 bad = smB + ((n0 + rib) * ASTR + (mb ? 8 : 0)) * 2;
        ldmatrix_x2(bf0, bad);       // k-step 0 (cols 0..15)
        ldmatrix_x2(bf1, bad + 32);  // k-step 1 (cols 16..31)

        // feature indices for this thread in this tile (f0 even => same i for f0,f0+1)
        int f0 = n0 + dlo;
        int i = f0 / 10;          // may be 10 on pad tiles: reads Py[0], D==0 there
        int j0 = f0 - 10 * i;
        int oi = i;               // sP offset for Px[i]
        int oj = 10 + j0;         // sP offset for Py[j0]; Py[j0+1] at +1

        // mt = 0
        {
            float d0 = 0.f, d1 = 0.f, d2 = 0.f, d3 = 0.f;
            mma_bf16(d0, d1, d2, d3, afr[0][0], bf0);
            mma_bf16(d0, d1, d2, d3, afr[0][1], bf1);
            float px0 = pr00[oi], py00 = pr00[oj], py01 = pr00[oj + 1];
            float px1 = pr01[oi], py10 = pr01[oj], py11 = pr01[oj + 1];
            acc00 = fmaf(px0, fmaf(d1, py01, d0 * py00), acc00);
            acc01 = fmaf(px1, fmaf(d3, py11, d2 * py10), acc01);
        }
        // mt = 1
        {
            float d0 = 0.f, d1 = 0.f, d2 = 0.f, d3 = 0.f;
            mma_bf16(d0, d1, d2, d3, afr[1][0], bf0);
            mma_bf16(d0, d1, d2, d3, afr[1][1], bf1);
            float px0 = pr10[oi], py00 = pr10[oj], py01 = pr10[oj + 1];
            float px1 = pr11[oi], py10 = pr11[oj], py11 = pr11[oj + 1];
            acc10 = fmaf(px0, fmaf(d1, py01, d0 * py00), acc10);
            acc11 = fmaf(px1, fmaf(d3, py11, d2 * py10), acc11);
        }
    }

    // ---- reduce across the 4 lanes of each quad (feature-subsets) ----
    acc00 += __shfl_xor_sync(0xFFFFFFFFu, acc00, 1);
    acc00 += __shfl_xor_sync(0xFFFFFFFFu, acc00, 2);
    acc01 += __shfl_xor_sync(0xFFFFFFFFu, acc01, 1);
    acc01 += __shfl_xor_sync(0xFFFFFFFFu, acc01, 2);
    acc10 += __shfl_xor_sync(0xFFFFFFFFu, acc10, 1);
    acc10 += __shfl_xor_sync(0xFFFFFFFFu, acc10, 2);
    acc11 += __shfl_xor_sync(0xFFFFFFFFu, acc11, 1);
    acc11 += __shfl_xor_sync(0xFFFFFFFFu, acc11, 2);

    if ((lane & 3) == 0) {
        int p0 = blockIdx.x * TPB + rg;
        if (p0 < N) out[p0] = acc00 + bb;
        if (p0 + 8 < N) out[p0 + 8] = acc01 + bb;
        if (p0 + 16 < N) out[p0 + 16] = acc10 + bb;
        if (p0 + 24 < N) out[p0 + 24] = acc11 + bb;
    }
}

extern "C" void kernel_launch(void* const* d_in, const int* in_sizes, int n_in,
                              void* d_out, int out_size) {
    int ib = -1, ix = -1, iw = -1;
    int max_sz = -1;
    for (int i = 0; i < n_in; i++) {
        if (in_sizes[i] == 1 && ib < 0) ib = i;
        else if (in_sizes[i] > max_sz) { max_sz = in_sizes[i]; ix = i; }
    }
    for (int i = 0; i < n_in; i++) {
        if (i != ib && i != ix) { iw = i; break; }
    }

    const float* x = (const float*)d_in[ix];
    const float* W = (const float*)d_in[iw];
    const float* b = (const float*)d_in[ib];
    float* out = (float*)d_out;

    int N = in_sizes[ix] / 3;
    int grid = (N + TPB - 1) / TPB;  // 128 points per CTA

    poly_mma_kernel<<<grid, TPB>>>(x, W, b, out, N);
}

// round 15
// speedup vs baseline: 1.1458x; 1.0179x over previous
#include <cuda_runtime.h>
#include <cuda_bf16.h>
#include <cstdint>

// MultiVariatePoly via mma.sync (HMMA) bf16 split-2 GEMM, fused epilogue.
// Per 128-point CTA: D[pt, f(i,j)] = A[128,32] @ B[104,32]^T
//   A row (point):   [Zhi(10) | Zlo(10) | Zhi(10) | 0 0]
//   B row (feature): [Whi(10) | Whi(10) | Wlo(10) | 0 0]
// Coefficients Px[i]*Py[j] applied to D fragments in the mma loop; quad
// shfl-reduce; one barrier; 29 KB smem.
// R15: B via single ldmatrix.x4/tile, Py pairs via ld.shared.v2.f32,
// precomputed u32 shared addresses.

#define NP1 10
#define TPB 128
#define ASTR 40    // bf16 per A/B row (80 B)
#define BROWS 104  // 13 n8-tiles
#define PSTR 20    // floats per sP row: Px[10] | Py[10]

typedef uint32_t u32;

__device__ __forceinline__ u32 smem_u32(const void* p) {
    u32 a;
    asm("{ .reg .u64 t; cvta.to.shared.u64 t, %1; cvt.u32.u64 %0, t; }" : "=r"(a) : "l"(p));
    return a;
}
__device__ __forceinline__ void ldmatrix_x4(u32* r, u32 addr) {
    asm volatile("ldmatrix.sync.aligned.m8n8.x4.shared.b16 {%0,%1,%2,%3}, [%4];"
                 : "=r"(r[0]), "=r"(r[1]), "=r"(r[2]), "=r"(r[3]) : "r"(addr));
}
__device__ __forceinline__ float lds_f32(u32 a) {
    float v; asm("ld.shared.f32 %0, [%1];" : "=f"(v) : "r"(a)); return v;
}
__device__ __forceinline__ float2 lds_f32x2(u32 a) {
    float2 v; asm("ld.shared.v2.f32 {%0,%1}, [%2];" : "=f"(v.x), "=f"(v.y) : "r"(a)); return v;
}
__device__ __forceinline__ void mma_bf16(float& d0, float& d1, float& d2, float& d3,
                                         const u32* a, const u32* b) {
    asm volatile(
        "mma.sync.aligned.m16n8k16.row.col.f32.bf16.bf16.f32 "
        "{%0,%1,%2,%3}, {%4,%5,%6,%7}, {%8,%9}, {%0,%1,%2,%3};"
        : "+f"(d0), "+f"(d1), "+f"(d2), "+f"(d3)
        : "r"(a[0]), "r"(a[1]), "r"(a[2]), "r"(a[3]), "r"(b[0]), "r"(b[1]));
}

__device__ __forceinline__ void legendre1(float x, float P[NP1]) {
    P[0] = 1.0f;
    P[1] = x;
#pragma unroll
    for (int k = 1; k < NP1 - 1; k++) {
        const float c1 = (float)(2 * k + 1) / (float)(k + 1);
        const float c2 = -(float)k / (float)(k + 1);
        P[k + 1] = c1 * x * P[k] + c2 * P[k - 1];
    }
}

__global__ void __launch_bounds__(TPB, 6)
poly_mma_kernel(const float* __restrict__ x, const float* __restrict__ W,
                const float* __restrict__ bptr, float* __restrict__ out, int N) {
    __shared__ __align__(16) __nv_bfloat16 sA[128 * ASTR];    // 10 KB
    __shared__ __align__(16) __nv_bfloat16 sB[BROWS * ASTR];  //  8.1 KB
    __shared__ __align__(8) float sP[128 * PSTR];             // 10 KB: Px|Py per point

    const int tid = threadIdx.x;
    const int lane = tid & 31;
    const int wrp = tid >> 5;
    const u32 smA = smem_u32(sA);
    const u32 smB = smem_u32(sB);
    const u32 smP = smem_u32(sP);

    // ---- per-point setup ----
    int p = blockIdx.x * TPB + tid;
    int pc = (p < N) ? p : (N - 1);
    float x0 = x[3 * pc + 0], x1 = x[3 * pc + 1], x2 = x[3 * pc + 2];
    float bb = *bptr;

    {
        float Px[NP1], Py[NP1], Pz[NP1];
        legendre1(x0, Px);
        legendre1(x1, Py);
        legendre1(x2, Pz);

        float2* prow = reinterpret_cast<float2*>(sP + tid * PSTR);
#pragma unroll
        for (int k = 0; k < 5; k++) prow[k] = make_float2(Px[2 * k], Px[2 * k + 1]);
#pragma unroll
        for (int k = 0; k < 5; k++) prow[5 + k] = make_float2(Py[2 * k], Py[2 * k + 1]);

        __nv_bfloat16 zh[NP1], zl[NP1];
#pragma unroll
        for (int k = 0; k < NP1; k++) {
            zh[k] = __float2bfloat16(Pz[k]);
            zl[k] = __float2bfloat16(Pz[k] - __bfloat162float(zh[k]));
        }
        __nv_bfloat162* row = reinterpret_cast<__nv_bfloat162*>(sA + tid * ASTR);
#pragma unroll
        for (int cc = 0; cc < 5; cc++) {
            __nv_bfloat162 v; v.x = zh[2 * cc]; v.y = zh[2 * cc + 1];
            row[cc] = v;
        }
#pragma unroll
        for (int cc = 0; cc < 5; cc++) {
            __nv_bfloat162 v; v.x = zl[2 * cc]; v.y = zl[2 * cc + 1];
            row[5 + cc] = v;
        }
#pragma unroll
        for (int cc = 0; cc < 5; cc++) {
            __nv_bfloat162 v; v.x = zh[2 * cc]; v.y = zh[2 * cc + 1];
            row[10 + cc] = v;
        }
        __nv_bfloat162 z2; z2.x = __float2bfloat16(0.f); z2.y = z2.x;
        row[15] = z2;  // cols 30,31 must be 0 for ldmatrix reads
    }

    // ---- B row (feature tid): [whi | whi | wlo | 0 0]; rows 100..103 zero ----
    if (tid < BROWS) {
        __nv_bfloat162* row = reinterpret_cast<__nv_bfloat162*>(sB + tid * ASTR);
        if (tid < 100) {
            const float* wr = W + 10 * tid;
            __nv_bfloat16 wh[NP1], wl[NP1];
#pragma unroll
            for (int k = 0; k < NP1; k++) {
                float w = wr[k];
                wh[k] = __float2bfloat16(w);
                wl[k] = __float2bfloat16(w - __bfloat162float(wh[k]));
            }
#pragma unroll
            for (int cc = 0; cc < 5; cc++) {
                __nv_bfloat162 v; v.x = wh[2 * cc]; v.y = wh[2 * cc + 1];
                row[cc] = v;
                row[5 + cc] = v;
            }
#pragma unroll
            for (int cc = 0; cc < 5; cc++) {
                __nv_bfloat162 v; v.x = wl[2 * cc]; v.y = wl[2 * cc + 1];
                row[10 + cc] = v;
            }
            __nv_bfloat162 z2; z2.x = __float2bfloat16(0.f); z2.y = z2.x;
            row[15] = z2;
        } else {
            __nv_bfloat162 z2; z2.x = __float2bfloat16(0.f); z2.y = z2.x;
#pragma unroll
            for (int cc = 0; cc < 16; cc++) row[cc] = z2;
        }
    }
    __syncthreads();  // the only barrier

    // ---- A fragments (verified mapping) ----
    u32 afr[2][2][4];
    {
        int m = lane >> 3, ri = lane & 7;
        int arow_base = wrp * 32 + ri + ((m & 1) << 3);
        int acol_off = (m & 2) ? 8 : 0;
#pragma unroll
        for (int mt = 0; mt < 2; mt++)
#pragma unroll
            for (int ks = 0; ks < 2; ks++) {
                u32 ad = smA + ((arow_base + 16 * mt) * ASTR + ks * 16 + acol_off) * 2;
                ldmatrix_x4(afr[mt][ks], ad);
            }
    }

    // B ldmatrix.x4 lane->addr: matrix m = lane>>3 at bf16-col 8m, row n0 + lane&7.
    // r = {cols0-7, 8-15, 16-23, 24-31} => bf0 = {r0,r1} (k-step0), bf1 = {r2,r3}.
    const u32 browband = smB + ((lane & 7) * ASTR + 8 * (lane >> 3)) * 2;

    // Precomputed sP row addresses for the 4 points this thread's fragments touch.
    const int rg = wrp * 32 + (lane >> 2);
    const u32 pb00 = smP + (rg + 0) * (PSTR * 4);
    const u32 pb01 = smP + (rg + 8) * (PSTR * 4);
    const u32 pb10 = smP + (rg + 16) * (PSTR * 4);
    const u32 pb11 = smP + (rg + 24) * (PSTR * 4);

    const int dlo = 2 * (lane & 3);  // feature offset within n8-tile (even)

    float acc00 = 0.f, acc01 = 0.f, acc10 = 0.f, acc11 = 0.f;

#pragma unroll
    for (int nt = 0; nt < 13; nt++) {
        u32 bq[4];
        ldmatrix_x4(bq, browband + nt * (8 * ASTR * 2));

        int f0 = nt * 8 + dlo;
        int i = f0 / 10;           // ==10 only on pad lanes (D==0 there)
        int j0 = f0 - 10 * i;
        u32 oi4 = (u32)(i * 4);
        u32 oj4 = (u32)((10 + j0) * 4);

        // mt = 0
        {
            float d0 = 0.f, d1 = 0.f, d2 = 0.f, d3 = 0.f;
            mma_bf16(d0, d1, d2, d3, afr[0][0], bq);
            mma_bf16(d0, d1, d2, d3, afr[0][1], bq + 2);
            float px0 = lds_f32(pb00 + oi4);
            float2 py0 = lds_f32x2(pb00 + oj4);
            float px1 = lds_f32(pb01 + oi4);
            float2 py1 = lds_f32x2(pb01 + oj4);
            acc00 = fmaf(px0, fmaf(d1, py0.y, d0 * py0.x), acc00);
            acc01 = fmaf(px1, fmaf(d3, py1.y, d2 * py1.x), acc01);
        }
        // mt = 1
        {
            float d0 = 0.f, d1 = 0.f, d2 = 0.f, d3 = 0.f;
            mma_bf16(d0, d1, d2, d3, afr[1][0], bq);
            mma_bf16(d0, d1, d2, d3, afr[1][1], bq + 2);
            float px0 = lds_f32(pb10 + oi4);
            float2 py0 = lds_f32x2(pb10 + oj4);
            float px1 = lds_f32(pb11 + oi4);
            float2 py1 = lds_f32x2(pb11 + oj4);
            acc10 = fmaf(px0, fmaf(d1, py0.y, d0 * py0.x), acc10);
            acc11 = fmaf(px1, fmaf(d3, py1.y, d2 * py1.x), acc11);
        }
    }

    // ---- reduce across the 4 lanes of each quad ----
    acc00 += __shfl_xor_sync(0xFFFFFFFFu, acc00, 1);
    acc00 += __shfl_xor_sync(0xFFFFFFFFu, acc00, 2);
    acc01 += __shfl_xor_sync(0xFFFFFFFFu, acc01, 1);
    acc01 += __shfl_xor_sync(0xFFFFFFFFu, acc01, 2);
    acc10 += __shfl_xor_sync(0xFFFFFFFFu, acc10, 1);
    acc10 += __shfl_xor_sync(0xFFFFFFFFu, acc10, 2);
    acc11 += __shfl_xor_sync(0xFFFFFFFFu, acc11, 1);
    acc11 += __shfl_xor_sync(0xFFFFFFFFu, acc11, 2);

    if ((lane & 3) == 0) {
        int p0 = blockIdx.x * TPB + rg;
        if (p0 < N) out[p0] = acc00 + bb;
        if (p0 + 8 < N) out[p0 + 8] = acc01 + bb;
        if (p0 + 16 < N) out[p0 + 16] = acc10 + bb;
        if (p0 + 24 < N) out[p0 + 24] = acc11 + bb;
    }
}

extern "C" void kernel_launch(void* const* d_in, const int* in_sizes, int n_in,
                              void* d_out, int out_size) {
    int ib = -1, ix = -1, iw = -1;
    int max_sz = -1;
    for (int i = 0; i < n_in; i++) {
        if (in_sizes[i] == 1 && ib < 0) ib = i;
        else if (in_sizes[i] > max_sz) { max_sz = in_sizes[i]; ix = i; }
    }
    for (int i = 0; i < n_in; i++) {
        if (i != ib && i != ix) { iw = i; break; }
    }

    const float* x = (const float*)d_in[ix];
    const float* W = (const float*)d_in[iw];
    const float* b = (const float*)d_in[ib];
    float* out = (float*)d_out;

    int N = in_sizes[ix] / 3;
    int grid = (N + TPB - 1) / TPB;  // 128 points per CTA

    poly_mma_kernel<<<grid, TPB>>>(x, W, b, out, N);
}